// round 15
// baseline (speedup 1.0000x reference)
#include <cuda_runtime.h>
#include <stdint.h>
#include <math.h>

#define NB 2
#define NS 2048
#define ND 1024
#define NH 16
#define NDK 64

// Scratch: projected Q/K/V [B,S,D] fp32 (head h = cols h*64..h*64+63),
// plus full score matrix in order-preserving mono-u32 [BH][S][S] (512 MB).
__device__ float g_Qp[NB * NS * ND];
__device__ float g_Kp[NB * NS * ND];
__device__ float g_Vp[NB * NS * ND];
__device__ unsigned g_S[(size_t)NB * NH * NS * NS];

// ---------------------------------------------------------------------------
// Helpers
// ---------------------------------------------------------------------------
__device__ __forceinline__ float warp_max(float v) {
#pragma unroll
    for (int off = 16; off > 0; off >>= 1)
        v = fmaxf(v, __shfl_xor_sync(0xffffffffu, v, off));
    return v;
}
__device__ __forceinline__ float warp_sum(float v) {
#pragma unroll
    for (int off = 16; off > 0; off >>= 1)
        v += __shfl_xor_sync(0xffffffffu, v, off);
    return v;
}
// Monotone float<->uint transform: u-order == float-order (finite values).
__device__ __forceinline__ unsigned f2mono(float f) {
    unsigned b = __float_as_uint(f);
    return (b & 0x80000000u) ? ~b : (b | 0x80000000u);
}
__device__ __forceinline__ float mono2f(unsigned u) {
    unsigned b = (u & 0x80000000u) ? (u ^ 0x80000000u) : ~u;
    return __uint_as_float(b);
}
// Packed dual-FMA: acc.{lo,hi} += a.{lo,hi} * b.{lo,hi}
__device__ __forceinline__ void ffma2(unsigned long long& acc,
                                      unsigned long long a,
                                      unsigned long long b) {
    asm("fma.rn.f32x2 %0, %1, %2, %0;" : "+l"(acc) : "l"(a), "l"(b));
}
// Duplicate a float into both halves of a packed f32x2
__device__ __forceinline__ unsigned long long dup2(float x) {
    unsigned long long r;
    asm("mov.b64 %0, {%1, %1};" : "=l"(r) : "f"(x));
    return r;
}
union F4U2 { float4 f; unsigned long long u[2]; float s[4]; };

// tf32 split: hi = rna_tf32(x), lo = rna_tf32(x - hi). (hi+lo) ~ x to ~2^-22.
__device__ __forceinline__ void tf32_split(float x, unsigned& hb, unsigned& lb) {
    asm("cvt.rna.tf32.f32 %0, %1;" : "=r"(hb) : "f"(x));
    float hf = __uint_as_float(hb);
    asm("cvt.rna.tf32.f32 %0, %1;" : "=r"(lb) : "f"(x - hf));
}

// m16n8k4 tf32 mma (unambiguous fragment layout: a0=(gid,tig), a1=(gid+8,tig),
// b0=(tig,gid), d = {(gid,2tig),(gid,2tig+1),(gid+8,2tig),(gid+8,2tig+1)})
__device__ __forceinline__ void mma_tf32_k4(float* d, unsigned a0, unsigned a1,
                                            unsigned b0) {
    asm("mma.sync.aligned.m16n8k4.row.col.f32.tf32.tf32.f32 "
        "{%0,%1,%2,%3}, {%4,%5}, {%6}, {%0,%1,%2,%3};"
        : "+f"(d[0]), "+f"(d[1]), "+f"(d[2]), "+f"(d[3])
        : "r"(a0), "r"(a1), "r"(b0));
}

// ---------------------------------------------------------------------------
// Projection GEMM (FFMA2): C = relu(A @ W + bias), M=4096, N=K=1024, x3.
// (R7 version, local optimum — verbatim)
// ---------------------------------------------------------------------------
__global__ __launch_bounds__(256, 2) void proj_kernel(
    const float* __restrict__ X0, const float* __restrict__ W0, const float* __restrict__ B0,
    const float* __restrict__ X1, const float* __restrict__ W1, const float* __restrict__ B1,
    const float* __restrict__ X2, const float* __restrict__ W2, const float* __restrict__ B2)
{
    const int N = ND, K = ND;
    const int z = blockIdx.z;
    const float* A    = (z == 0) ? X0 : (z == 1) ? X1 : X2;
    const float* W    = (z == 0) ? W0 : (z == 1) ? W1 : W2;
    const float* bias = (z == 0) ? B0 : (z == 1) ? B1 : B2;
    float* C          = (z == 0) ? g_Qp : (z == 1) ? g_Kp : g_Vp;

    __shared__ float As[2][16][128];
    __shared__ float Bs[2][16][128];

    const int tid = threadIdx.x;
    const int tx = tid & 15;
    const int ty = tid >> 4;
    const int brow = blockIdx.y * 128;
    const int bcol = blockIdx.x * 128;

    const int ar = tid >> 1;
    const int ak = (tid & 1) << 3;
    const int wr = tid >> 4;
    const int wc = (tid & 15) << 3;

    unsigned long long accp[8][4];
#pragma unroll
    for (int i = 0; i < 8; i++)
#pragma unroll
        for (int q = 0; q < 4; q++) accp[i][q] = 0ull;

    const float* Aptr = A + (size_t)(brow + ar) * K + ak;
    const float* Wptr = W + (size_t)wr * N + bcol + wc;

    float4 a0 = *(const float4*)(Aptr);
    float4 a1 = *(const float4*)(Aptr + 4);
    float4 w0 = *(const float4*)(Wptr);
    float4 w1 = *(const float4*)(Wptr + 4);

    int p = 0;
    for (int k0 = 0; k0 < K; k0 += 16) {
        As[p][ak + 0][ar] = a0.x;
        As[p][ak + 1][ar] = a0.y;
        As[p][ak + 2][ar] = a0.z;
        As[p][ak + 3][ar] = a0.w;
        As[p][ak + 4][ar] = a1.x;
        As[p][ak + 5][ar] = a1.y;
        As[p][ak + 6][ar] = a1.z;
        As[p][ak + 7][ar] = a1.w;
        *(float4*)&Bs[p][wr][wc] = w0;
        *(float4*)&Bs[p][wr][wc + 4] = w1;
        __syncthreads();
        if (k0 + 16 < K) {
            a0 = *(const float4*)(Aptr + k0 + 16);
            a1 = *(const float4*)(Aptr + k0 + 20);
            w0 = *(const float4*)(Wptr + (size_t)(k0 + 16) * N);
            w1 = *(const float4*)(Wptr + (size_t)(k0 + 16) * N + 4);
        }
#pragma unroll
        for (int k = 0; k < 16; k++) {
            float4 av0 = *(const float4*)&As[p][k][ty * 4];
            float4 av1 = *(const float4*)&As[p][k][64 + ty * 4];
            F4U2 b0, b1;
            b0.f = *(const float4*)&Bs[p][k][tx * 4];
            b1.f = *(const float4*)&Bs[p][k][64 + tx * 4];
            unsigned long long bp[4] = {b0.u[0], b0.u[1], b1.u[0], b1.u[1]};
            float arr[8] = {av0.x, av0.y, av0.z, av0.w, av1.x, av1.y, av1.z, av1.w};
#pragma unroll
            for (int i = 0; i < 8; i++) {
                unsigned long long ad = dup2(arr[i]);
#pragma unroll
                for (int q = 0; q < 4; q++) ffma2(accp[i][q], ad, bp[q]);
            }
        }
        p ^= 1;
    }

#pragma unroll
    for (int i = 0; i < 8; i++) {
        const int r = brow + ((i < 4) ? (ty * 4 + i) : (64 + ty * 4 + (i - 4)));
        const float2* ap = (const float2*)&accp[i][0];
        {
            const int c = bcol + tx * 4;
            float4 v;
            v.x = fmaxf(ap[0].x + bias[c + 0], 0.0f);
            v.y = fmaxf(ap[0].y + bias[c + 1], 0.0f);
            v.z = fmaxf(ap[1].x + bias[c + 2], 0.0f);
            v.w = fmaxf(ap[1].y + bias[c + 3], 0.0f);
            *(float4*)(C + (size_t)r * N + c) = v;
        }
        {
            const int c = bcol + 64 + tx * 4;
            float4 v;
            v.x = fmaxf(ap[2].x + bias[c + 0], 0.0f);
            v.y = fmaxf(ap[2].y + bias[c + 1], 0.0f);
            v.z = fmaxf(ap[3].x + bias[c + 2], 0.0f);
            v.w = fmaxf(ap[3].y + bias[c + 3], 0.0f);
            *(float4*)(C + (size_t)r * N + c) = v;
        }
    }
}

// ---------------------------------------------------------------------------
// Phase A: score GEMM on mma.sync tf32, 4-term split (near-fp32 accuracy).
// Per (b,h): S = (Qh @ Kh^T)/8 as mono-u32. CTA tile 128x128; warp tile
// 32(M)x64(N); warps 4x2. K=64 processed in 8 chunks of 8 original k; each
// original k expands to a k4 quad: A=[hi,lo,hi,lo], B=[hi,hi,lo,lo] ->
// one m16n8k4 mma accumulates all 4 split terms in fp32.
// Grid = (16, 16, 32).
// ---------------------------------------------------------------------------
#define SCP 36   // smem row stride (32 k4 + pad), 144B = 16B-aligned rows
__global__ __launch_bounds__(256, 2) void score_tf32_kernel()
{
    __shared__ float Qs[128][SCP];   // [m][k4] tf32-as-f32, A quads
    __shared__ float Ks[128][SCP];   // [n][k4] tf32-as-f32, B quads

    const int tid = threadIdx.x;
    const int warp = tid >> 5, lane = tid & 31;
    const int wm = warp & 3;          // warp row (4 x 32 rows)
    const int wn = warp >> 2;         // warp col (2 x 64 cols)
    const int gid = lane >> 2, tig = lane & 3;

    const int bh = blockIdx.z;
    const int b = bh >> 4, h = bh & 15;
    const int brow = blockIdx.y * 128;
    const int bcol = blockIdx.x * 128;

    const float* Qb = g_Qp + (size_t)b * NS * ND + h * NDK;
    const float* Kb = g_Kp + (size_t)b * NS * ND + h * NDK;

    float acc[2][8][4];
#pragma unroll
    for (int mt = 0; mt < 2; mt++)
#pragma unroll
        for (int nt = 0; nt < 8; nt++)
#pragma unroll
            for (int c = 0; c < 4; c++) acc[mt][nt][c] = 0.0f;

    const int sr = tid >> 1;          // staging row 0..127
    const int sw = tid & 1;           // staging k-half (float4 at k 0-3 / 4-7)

    for (int ch = 0; ch < 8; ch++) {
        __syncthreads();
        // stage 8 original k columns as k4 quads
        {
            float4 q = *(const float4*)(Qb + (size_t)(brow + sr) * ND + ch * 8 + sw * 4);
            float4 kv = *(const float4*)(Kb + (size_t)(bcol + sr) * ND + ch * 8 + sw * 4);
            const float qs[4] = {q.x, q.y, q.z, q.w};
            const float ks[4] = {kv.x, kv.y, kv.z, kv.w};
#pragma unroll
            for (int j = 0; j < 4; j++) {
                unsigned qh, ql, kh, kl;
                tf32_split(qs[j], qh, ql);
                tf32_split(ks[j], kh, kl);
                float qhf = __uint_as_float(qh), qlf = __uint_as_float(ql);
                float khf = __uint_as_float(kh), klf = __uint_as_float(kl);
                *(float4*)&Qs[sr][sw * 16 + j * 4] = make_float4(qhf, qlf, qhf, qlf);
                *(float4*)&Ks[sr][sw * 16 + j * 4] = make_float4(khf, khf, klf, klf);
            }
        }
        __syncthreads();

        // 8 mma k-steps (one original k each)
#pragma unroll
        for (int kq = 0; kq < 8; kq++) {
            unsigned a0[2], a1[2];
#pragma unroll
            for (int mt = 0; mt < 2; mt++) {
                a0[mt] = __float_as_uint(Qs[wm * 32 + mt * 16 + gid][kq * 4 + tig]);
                a1[mt] = __float_as_uint(Qs[wm * 32 + mt * 16 + 8 + gid][kq * 4 + tig]);
            }
#pragma unroll
            for (int nt = 0; nt < 8; nt++) {
                const unsigned b0 =
                    __float_as_uint(Ks[wn * 64 + nt * 8 + gid][kq * 4 + tig]);
                mma_tf32_k4(acc[0][nt], a0[0], a1[0], b0);
                mma_tf32_k4(acc[1][nt], a0[1], a1[1], b0);
            }
        }
    }

    // epilogue: scale by 1/8, mono-transform, store
    unsigned* Sb = g_S + (size_t)bh * NS * NS;
#pragma unroll
    for (int mt = 0; mt < 2; mt++) {
#pragma unroll
        for (int half = 0; half < 2; half++) {
            const int row = brow + wm * 32 + mt * 16 + half * 8 + gid;
            unsigned* srow = Sb + (size_t)row * NS + bcol + wn * 64;
#pragma unroll
            for (int nt = 0; nt < 8; nt++) {
                uint2 u;
                u.x = f2mono(acc[mt][nt][half * 2 + 0] * 0.125f);
                u.y = f2mono(acc[mt][nt][half * 2 + 1] * 0.125f);
                *(uint2*)(srow + nt * 8 + 2 * tig) = u;
            }
        }
    }
}

// ---------------------------------------------------------------------------
// Phase B: per (b,h,s) row — exact top-32 over the stored mono-u32 scores,
// softmax over survivors, V gather, output. One warp per row; 8-deep
// prefetch ring. (R13 version, verbatim)
// ---------------------------------------------------------------------------
__global__ __launch_bounds__(256) void select_kernel(float* __restrict__ out)
{
    __shared__ float swt[8][32];
    __shared__ int   svi[8][32];

    const int warp = threadIdx.x >> 5;
    const int lane = threadIdx.x & 31;
    const int job = blockIdx.x * 8 + warp;   // 0..65535
    const int bh = job >> 11;
    const int s  = job & 2047;
    const int b = bh >> 4, h = bh & 15;

    const unsigned* srow = g_S + (size_t)bh * NS * NS + (size_t)s * NS;

    // init list from first 32 candidates
    unsigned lu = srow[lane];
    int lidx = lane;
    unsigned umin = __reduce_min_sync(0xffffffffu, lu);
    int minlane = __ffs(__ballot_sync(0xffffffffu, lu == umin)) - 1;

    // 8-deep prefetch ring
    unsigned nxt[8];
#pragma unroll
    for (int j = 0; j < 8; j++) nxt[j] = srow[(1 + j) * 32 + lane];

#pragma unroll 8
    for (int t = 1; t < 64; t++) {
        const unsigned u = nxt[(t - 1) & 7];
        if (t + 8 < 64) nxt[(t - 1) & 7] = srow[(t + 8) * 32 + lane];
        const int base = t * 32;

        unsigned bal = __ballot_sync(0xffffffffu, u > umin);
        while (bal) {
            const int src = __ffs(bal) - 1;
            bal &= bal - 1;
            const unsigned uv = __shfl_sync(0xffffffffu, u, src);
            if (uv > umin) {             // umin warp-uniform -> uniform branch
                if (lane == minlane) { lu = uv; lidx = base + src; }
                umin = __reduce_min_sync(0xffffffffu, lu);
                minlane = __ffs(__ballot_sync(0xffffffffu, lu == umin)) - 1;
            }
        }
    }

    // softmax over the 32 survivors (== reference masked softmax: masked
    // entries contribute exp(-1e9 - max) == 0 in fp32)
    const float lval = mono2f(lu);
    const float m = warp_max(lval);
    const float e = __expf(lval - m);
    const float w = e / warp_sum(e);

    // publish (weight, index) via smem; gather loop uses LDS broadcasts
    swt[warp][lane] = w;
    svi[warp][lane] = lidx;
    __syncwarp();

    // AV gather: lane owns output dims (2*lane, 2*lane+1)
    const float* Vb = g_Vp + (size_t)b * NS * ND + h * NDK + lane * 2;
    float2 acc = make_float2(0.f, 0.f);
#pragma unroll
    for (int t = 0; t < 32; t++) {
        const int   vi = svi[warp][t];
        const float wt = swt[warp][t];
        const float2 v = *(const float2*)(Vb + (size_t)vi * ND);
        acc.x += wt * v.x;
        acc.y += wt * v.y;
    }

    *(float2*)(out + (size_t)(b * NS + s) * ND + h * NDK + lane * 2) = acc;
}

// ---------------------------------------------------------------------------
extern "C" void kernel_launch(void* const* d_in, const int* in_sizes, int n_in,
                              void* d_out, int out_size)
{
    const float* query = (const float*)d_in[0];
    const float* key   = (const float*)d_in[1];
    const float* value = (const float*)d_in[2];
    const float* Wq    = (const float*)d_in[3];
    const float* bq    = (const float*)d_in[4];
    const float* Wk    = (const float*)d_in[5];
    const float* bk    = (const float*)d_in[6];
    const float* Wv    = (const float*)d_in[7];
    const float* bv    = (const float*)d_in[8];
    float* out = (float*)d_out;

    dim3 pgrid(ND / 128, (NB * NS) / 128, 3);
    proj_kernel<<<pgrid, 256>>>(query, Wq, bq, key, Wk, bk, value, Wv, bv);

    dim3 sgrid(NS / 128, NS / 128, NB * NH);
    score_tf32_kernel<<<sgrid, 256>>>();

    select_kernel<<<(NB * NH * NS) / 8, 256>>>(out);
}